// round 4
// baseline (speedup 1.0000x reference)
#include <cuda_runtime.h>
#include <cuda_fp16.h>
#include <cstdint>

// Block-diagonal linear: y[n, b*64+j] = sum_{k<64} x[n, b*64+k] * w[b*64+j, b*64+k]
// fp16 m16n8k16 mma with 2-way hi/lo split, 3 terms (hh+hl+lh): ~3e-7 rel err.
// R4: persistent CTAs (8 row-tiles each), W split once per CTA, B fragments
// pinned in registers (no B LDS in mainloop), double-buffered X staging.

#define N_FEAT   4096
#define BLK      64
#define NBLK     64
#define TROWS    64
#define MULTI    8
#define THREADS  256
#define XSP      36                 // u32 stride: frag LDS banks (4g+tq)%32 all distinct
#define RHALF    (TROWS * XSP)      // 2304 u32 per hi or lo plane

__device__ __forceinline__ void split_pack2(float a, float b, uint32_t& hi, uint32_t& lo) {
    __half ha = __float2half_rn(a), hb = __float2half_rn(b);
    __half la = __float2half_rn(a - __half2float(ha));
    __half lb = __float2half_rn(b - __half2float(hb));
    __half2 H = __halves2half2(ha, hb);
    __half2 L = __halves2half2(la, lb);
    hi = *(uint32_t*)&H;
    lo = *(uint32_t*)&L;
}

__device__ __forceinline__ void mma_f16(float c[4],
                                        uint32_t a0, uint32_t a1, uint32_t a2, uint32_t a3,
                                        uint32_t b0, uint32_t b1) {
    asm volatile(
        "mma.sync.aligned.m16n8k16.row.col.f32.f16.f16.f32 "
        "{%0,%1,%2,%3}, {%4,%5,%6,%7}, {%8,%9}, {%0,%1,%2,%3};"
        : "+f"(c[0]), "+f"(c[1]), "+f"(c[2]), "+f"(c[3])
        : "r"(a0), "r"(a1), "r"(a2), "r"(a3), "r"(b0), "r"(b1));
}

__global__ __launch_bounds__(THREADS)
void sl_blockdiag_kernel(const float* __restrict__ x,
                         const float* __restrict__ w,
                         float* __restrict__ out) {
    // two regions, each holds one 64x64 tile as hi-plane + lo-plane (f16x2 packed)
    __shared__ uint32_t smem[2][2 * RHALF];   // 36864 B total

    const int b  = blockIdx.x % NBLK;         // diagonal block
    const int tg = blockIdx.x / NBLK;         // tile-group (512 rows)
    const int tid = threadIdx.x;
    const size_t colbase = (size_t)b * BLK;
    const size_t row0cta = (size_t)tg * (TROWS * MULTI);

    // ---- stage + split W_b once, into region 1 ----
    {
        uint32_t* wh = smem[1];
        uint32_t* wl = smem[1] + RHALF;
        #pragma unroll
        for (int i = tid; i < BLK * 16; i += THREADS) {
            int r = i >> 4, q = i & 15;
            float4 v = *(const float4*)(w + (colbase + r) * N_FEAT + colbase + q * 4);
            uint32_t h0, l0, h1, l1;
            split_pack2(v.x, v.y, h0, l0);
            split_pack2(v.z, v.w, h1, l1);
            wh[r * XSP + 2 * q] = h0;  wh[r * XSP + 2 * q + 1] = h1;
            wl[r * XSP + 2 * q] = l0;  wl[r * XSP + 2 * q + 1] = l1;
        }
    }
    __syncthreads();

    const int wid  = tid >> 5;
    const int lane = tid & 31;
    const int g    = lane >> 2;    // groupID 0..7
    const int tq   = lane & 3;     // thread-in-group
    const int mg   = wid >> 1;     // 0..3 : which 16-row group
    const int nh   = wid & 1;      // 0..1 : which 32-col half
    const int m0   = mg * 16;

    // ---- B fragments -> registers (held for the whole CTA) ----
    uint32_t bh[4][4][2], bl[4][4][2];   // [nt][ks][reg]
    {
        const uint32_t* wh = smem[1];
        const uint32_t* wl = smem[1] + RHALF;
        #pragma unroll
        for (int nt = 0; nt < 4; nt++) {
            int nrow = (nh * 4 + nt) * 8 + g;     // B col-major: b = W[n][k]
            #pragma unroll
            for (int ks = 0; ks < 4; ks++) {
                int a = nrow * XSP + ks * 8 + tq;
                bh[nt][ks][0] = wh[a];  bh[nt][ks][1] = wh[a + 4];
                bl[nt][ks][0] = wl[a];  bl[nt][ks][1] = wl[a + 4];
            }
        }
    }

    // staging coords: thread -> row sr, 64B contiguous chunk (tid&3)
    const int sr = tid >> 2;
    const int sq = (tid & 3) * 4;

    // ---- stage X tile 0 into region 0 ----
    {
        const float4* src = (const float4*)(x + (row0cta + sr) * N_FEAT + colbase) + (tid & 3) * 4;
        uint32_t* xh = smem[0];
        uint32_t* xl = smem[0] + RHALF;
        #pragma unroll
        for (int j = 0; j < 4; j++) {
            float4 v = src[j];
            uint32_t h0, l0, h1, l1;
            split_pack2(v.x, v.y, h0, l0);
            split_pack2(v.z, v.w, h1, l1);
            int q = sq + j;
            xh[sr * XSP + 2 * q] = h0;  xh[sr * XSP + 2 * q + 1] = h1;
            xl[sr * XSP + 2 * q] = l0;  xl[sr * XSP + 2 * q + 1] = l1;
        }
    }
    __syncthreads();

    for (int t = 0; t < MULTI; t++) {
        // prefetch next tile into registers (hides DRAM latency under compute)
        float4 p[4];
        if (t + 1 < MULTI) {
            const float4* src = (const float4*)(x + (row0cta + (t + 1) * TROWS + sr) * N_FEAT + colbase)
                                + (tid & 3) * 4;
            #pragma unroll
            for (int j = 0; j < 4; j++) p[j] = src[j];
        }

        const uint32_t* xh = smem[t & 1];
        const uint32_t* xl = smem[t & 1] + RHALF;

        float c[4][4];
        #pragma unroll
        for (int i = 0; i < 4; i++)
            #pragma unroll
            for (int j = 0; j < 4; j++) c[i][j] = 0.f;

        #pragma unroll
        for (int ks = 0; ks < 4; ks++) {
            int a0 = (m0 + g)     * XSP + ks * 8 + tq;
            int a1 = (m0 + g + 8) * XSP + ks * 8 + tq;
            uint32_t ah0 = xh[a0], ah1 = xh[a1], ah2 = xh[a0 + 4], ah3 = xh[a1 + 4];
            uint32_t al0 = xl[a0], al1 = xl[a1], al2 = xl[a0 + 4], al3 = xl[a1 + 4];
            #pragma unroll
            for (int nt = 0; nt < 4; nt++) {
                mma_f16(c[nt], ah0, ah1, ah2, ah3, bh[nt][ks][0], bh[nt][ks][1]);  // hh
                mma_f16(c[nt], ah0, ah1, ah2, ah3, bl[nt][ks][0], bl[nt][ks][1]);  // hl
                mma_f16(c[nt], al0, al1, al2, al3, bh[nt][ks][0], bh[nt][ks][1]);  // lh
            }
        }

        // epilogue: C rows g/g+8, cols 2tq/2tq+1 per n-tile
        const size_t row = row0cta + (size_t)t * TROWS + m0 + g;
        #pragma unroll
        for (int nt = 0; nt < 4; nt++) {
            size_t col = colbase + (nh * 4 + nt) * 8 + tq * 2;
            *(float2*)(out + row * N_FEAT + col)       = make_float2(c[nt][0], c[nt][1]);
            *(float2*)(out + (row + 8) * N_FEAT + col) = make_float2(c[nt][2], c[nt][3]);
        }

        // split + store next tile into the other region
        if (t + 1 < MULTI) {
            uint32_t* nxh = smem[(t + 1) & 1];
            uint32_t* nxl = nxh + RHALF;
            #pragma unroll
            for (int j = 0; j < 4; j++) {
                uint32_t h0, l0, h1, l1;
                split_pack2(p[j].x, p[j].y, h0, l0);
                split_pack2(p[j].z, p[j].w, h1, l1);
                int q = sq + j;
                nxh[sr * XSP + 2 * q] = h0;  nxh[sr * XSP + 2 * q + 1] = h1;
                nxl[sr * XSP + 2 * q] = l0;  nxl[sr * XSP + 2 * q + 1] = l1;
            }
        }
        __syncthreads();
    }
}

extern "C" void kernel_launch(void* const* d_in, const int* in_sizes, int n_in,
                              void* d_out, int out_size) {
    const float* x = (const float*)d_in[0];
    const float* w = (const float*)d_in[1];
    float* out = (float*)d_out;

    const int n_rows = in_sizes[0] / N_FEAT;                 // 8192
    const int tile_groups = n_rows / (TROWS * MULTI);        // 16

    dim3 grid(NBLK * tile_groups);                           // 1024 CTAs
    sl_blockdiag_kernel<<<grid, THREADS>>>(x, w, out);
}

// round 5
// speedup vs baseline: 1.1389x; 1.1389x over previous
#include <cuda_runtime.h>
#include <cuda_fp16.h>
#include <cstdint>

// Block-diagonal linear: y[n, b*64+j] = sum_{k<64} x[n, b*64+k] * w[b*64+j, b*64+k]
// fp16 m16n8k16 mma, 2-way hi/lo split, 3 terms (hh+hl+lh): ~3e-7 rel err.
// R5: ldmatrix A fragments, STG moved out of barrier region, MULTI=4 (2048 CTAs),
// B fragments pinned in registers, W split once per CTA.

#define N_FEAT   4096
#define BLK      64
#define NBLK     64
#define TROWS    64
#define MULTI    4
#define THREADS  256
#define XSP      36                 // u32 stride: (4r+c)%32 all distinct -> conflict-free
#define RHALF    (TROWS * XSP)      // u32 per hi/lo plane

__device__ __forceinline__ void split_pack2(float a, float b, uint32_t& hi, uint32_t& lo) {
    __half ha = __float2half_rn(a), hb = __float2half_rn(b);
    __half la = __float2half_rn(a - __half2float(ha));
    __half lb = __float2half_rn(b - __half2float(hb));
    __half2 H = __halves2half2(ha, hb);
    __half2 L = __halves2half2(la, lb);
    hi = *(uint32_t*)&H;
    lo = *(uint32_t*)&L;
}

__device__ __forceinline__ void mma_f16(float c[4],
                                        uint32_t a0, uint32_t a1, uint32_t a2, uint32_t a3,
                                        uint32_t b0, uint32_t b1) {
    asm volatile(
        "mma.sync.aligned.m16n8k16.row.col.f32.f16.f16.f32 "
        "{%0,%1,%2,%3}, {%4,%5,%6,%7}, {%8,%9}, {%0,%1,%2,%3};"
        : "+f"(c[0]), "+f"(c[1]), "+f"(c[2]), "+f"(c[3])
        : "r"(a0), "r"(a1), "r"(a2), "r"(a3), "r"(b0), "r"(b1));
}

__device__ __forceinline__ void ldm_x4(uint32_t& r0, uint32_t& r1, uint32_t& r2, uint32_t& r3,
                                       uint32_t addr) {
    asm volatile("ldmatrix.sync.aligned.m8n8.x4.shared.b16 {%0,%1,%2,%3}, [%4];"
                 : "=r"(r0), "=r"(r1), "=r"(r2), "=r"(r3) : "r"(addr));
}

__global__ __launch_bounds__(THREADS, 2)
void sl_blockdiag_kernel(const float* __restrict__ x,
                         const float* __restrict__ w,
                         float* __restrict__ out) {
    __shared__ uint32_t smem[2][2 * RHALF];   // 36864 B; region 1 first holds W, then X buf

    const int b  = blockIdx.x % NBLK;
    const int tg = blockIdx.x / NBLK;
    const int tid = threadIdx.x;
    const size_t colbase = (size_t)b * BLK;
    const size_t row0cta = (size_t)tg * (TROWS * MULTI);

    // ---- stage + split W_b once into region 1 ----
    {
        uint32_t* wh = smem[1];
        uint32_t* wl = smem[1] + RHALF;
        #pragma unroll
        for (int i = tid; i < BLK * 16; i += THREADS) {
            int r = i >> 4, q = i & 15;
            float4 v = *(const float4*)(w + (colbase + r) * N_FEAT + colbase + q * 4);
            uint32_t h0, l0, h1, l1;
            split_pack2(v.x, v.y, h0, l0);
            split_pack2(v.z, v.w, h1, l1);
            wh[r * XSP + 2 * q] = h0;  wh[r * XSP + 2 * q + 1] = h1;
            wl[r * XSP + 2 * q] = l0;  wl[r * XSP + 2 * q + 1] = l1;
        }
    }
    __syncthreads();

    const int wid  = tid >> 5;
    const int lane = tid & 31;
    const int g    = lane >> 2;
    const int tq   = lane & 3;
    const int mg   = wid >> 1;
    const int nh   = wid & 1;
    const int m0   = mg * 16;

    // ---- B fragments -> registers (whole CTA lifetime) ----
    uint32_t bh[4][4][2], bl[4][4][2];   // [nt][ks][reg]
    {
        const uint32_t* wh = smem[1];
        const uint32_t* wl = smem[1] + RHALF;
        #pragma unroll
        for (int nt = 0; nt < 4; nt++) {
            int nrow = (nh * 4 + nt) * 8 + g;
            #pragma unroll
            for (int ks = 0; ks < 4; ks++) {
                int a = nrow * XSP + ks * 8 + tq;
                bh[nt][ks][0] = wh[a];  bh[nt][ks][1] = wh[a + 4];
                bl[nt][ks][0] = wl[a];  bl[nt][ks][1] = wl[a + 4];
            }
        }
    }

    // ldmatrix lane -> row address precompute (byte offset within a plane)
    const int lane7 = lane & 7;
    const int mat   = lane >> 3;
    const int arow  = m0 + lane7 + ((mat & 1) << 3);
    const int acolu = (mat >> 1) << 2;               // +4 u32 for k+8 half
    const uint32_t aoff = (uint32_t)(arow * XSP + acolu) * 4u;
    const uint32_t sb0  = (uint32_t)__cvta_generic_to_shared(&smem[0][0]);
    const uint32_t regbytes = 2u * RHALF * 4u;

    // staging coords: thread -> row sr, 64B chunk (tid&3)
    const int sr = tid >> 2;
    const int sq = (tid & 3) * 4;

    // ---- stage X tile 0 into region 0 ----
    {
        const float4* src = (const float4*)(x + (row0cta + sr) * N_FEAT + colbase) + (tid & 3) * 4;
        uint32_t* xh = smem[0];
        uint32_t* xl = smem[0] + RHALF;
        #pragma unroll
        for (int j = 0; j < 4; j++) {
            float4 v = src[j];
            uint32_t h0, l0, h1, l1;
            split_pack2(v.x, v.y, h0, l0);
            split_pack2(v.z, v.w, h1, l1);
            int q = sq + j;
            xh[sr * XSP + 2 * q] = h0;  xh[sr * XSP + 2 * q + 1] = h1;
            xl[sr * XSP + 2 * q] = l0;  xl[sr * XSP + 2 * q + 1] = l1;
        }
    }
    __syncthreads();

    for (int t = 0; t < MULTI; t++) {
        // prefetch next tile into registers
        float4 p[4];
        if (t + 1 < MULTI) {
            const float4* src = (const float4*)(x + (row0cta + (t + 1) * TROWS + sr) * N_FEAT + colbase)
                                + (tid & 3) * 4;
            #pragma unroll
            for (int j = 0; j < 4; j++) p[j] = src[j];
        }

        const uint32_t tb = sb0 + (uint32_t)(t & 1) * regbytes;

        float c[4][4];
        #pragma unroll
        for (int i = 0; i < 4; i++)
            #pragma unroll
            for (int j = 0; j < 4; j++) c[i][j] = 0.f;

        #pragma unroll
        for (int ks = 0; ks < 4; ks++) {
            const uint32_t ab = tb + aoff + (uint32_t)(ks * 8) * 4u;
            uint32_t ah0, ah1, ah2, ah3, al0, al1, al2, al3;
            ldm_x4(ah0, ah1, ah2, ah3, ab);
            ldm_x4(al0, al1, al2, al3, ab + RHALF * 4u);

            #pragma unroll
            for (int nt = 0; nt < 4; nt++)
                mma_f16(c[nt], ah0, ah1, ah2, ah3, bh[nt][ks][0], bh[nt][ks][1]);  // hh
            #pragma unroll
            for (int nt = 0; nt < 4; nt++)
                mma_f16(c[nt], ah0, ah1, ah2, ah3, bl[nt][ks][0], bl[nt][ks][1]);  // hl
            #pragma unroll
            for (int nt = 0; nt < 4; nt++)
                mma_f16(c[nt], al0, al1, al2, al3, bh[nt][ks][0], bh[nt][ks][1]);  // lh
        }

        // split + store next tile into the other region (before the barrier)
        if (t + 1 < MULTI) {
            uint32_t* nxh = smem[(t + 1) & 1];
            uint32_t* nxl = nxh + RHALF;
            #pragma unroll
            for (int j = 0; j < 4; j++) {
                uint32_t h0, l0, h1, l1;
                split_pack2(p[j].x, p[j].y, h0, l0);
                split_pack2(p[j].z, p[j].w, h1, l1);
                int q = sq + j;
                nxh[sr * XSP + 2 * q] = h0;  nxh[sr * XSP + 2 * q + 1] = h1;
                nxl[sr * XSP + 2 * q] = l0;  nxl[sr * XSP + 2 * q + 1] = l1;
            }
            __syncthreads();
        }

        // epilogue AFTER the barrier: overlaps next tile's prefetch + MMA
        const size_t row = row0cta + (size_t)t * TROWS + m0 + g;
        #pragma unroll
        for (int nt = 0; nt < 4; nt++) {
            size_t col = colbase + (nh * 4 + nt) * 8 + tq * 2;
            *(float2*)(out + row * N_FEAT + col)       = make_float2(c[nt][0], c[nt][1]);
            *(float2*)(out + (row + 8) * N_FEAT + col) = make_float2(c[nt][2], c[nt][3]);
        }
    }
}

extern "C" void kernel_launch(void* const* d_in, const int* in_sizes, int n_in,
                              void* d_out, int out_size) {
    const float* x = (const float*)d_in[0];
    const float* w = (const float*)d_in[1];
    float* out = (float*)d_out;

    const int n_rows = in_sizes[0] / N_FEAT;                 // 8192
    const int tile_groups = n_rows / (TROWS * MULTI);        // 32

    dim3 grid(NBLK * tile_groups);                           // 2048 CTAs
    sl_blockdiag_kernel<<<grid, THREADS>>>(x, w, out);
}